// round 6
// baseline (speedup 1.0000x reference)
#include <cuda_runtime.h>
#include <cstdint>

// SSIM loss, separable Gaussian 11x11 on fields {s,d,s^2,d^2}, s=x+y, d=x-y.
// cp.async double-buffered raw staging; 48-slot ring; vertical as two 32-row
// passes, 8 rows/thread on all 256 threads (compile-time ring slots via
// templates). Packed f32x2 math throughout.

namespace {
constexpr int WI = 512, HI = 512;
constexpr int SW = 64;              // strip width
constexpr int CH = 16;              // rows per chunk
constexpr int RAWW = 84;            // raw row stride in floats (80 used)
constexpr int RW4 = 64;             // ring row stride in float4
constexpr float C1c = 1e-4f;
constexpr float C2c = 9e-4f;
constexpr double NPIX = 25165824.0; // 32*3*512*512
constexpr unsigned NBLK = 8 * 8 * 96;
}

__device__ double g_accum;
__device__ unsigned g_done;

using u64 = unsigned long long;

__device__ __forceinline__ u64 pk(float a, float b) {
    u64 r; asm("mov.b64 %0, {%1, %2};" : "=l"(r) : "f"(a), "f"(b)); return r;
}
__device__ __forceinline__ void upk(float& a, float& b, u64 v) {
    asm("mov.b64 {%0, %1}, %2;" : "=f"(a), "=f"(b) : "l"(v));
}
__device__ __forceinline__ u64 ffma2(u64 a, u64 b, u64 c) {
    u64 d; asm("fma.rn.f32x2 %0, %1, %2, %3;" : "=l"(d) : "l"(a), "l"(b), "l"(c));
    return d;
}
__device__ __forceinline__ u64 fmul2(u64 a, u64 b) {
    u64 d; asm("mul.rn.f32x2 %0, %1, %2;" : "=l"(d) : "l"(a), "l"(b));
    return d;
}
__device__ __forceinline__ int SWZ4(int c) { return c ^ (((c) >> 3) & 7); }

__device__ __forceinline__ void cpasync16(uint32_t dst, const void* src, int srcsize) {
    asm volatile("cp.async.cg.shared.global [%0], [%1], 16, %2;"
                 :: "r"(dst), "l"(src), "r"(srcsize) : "memory");
}
#define CP_COMMIT()  asm volatile("cp.async.commit_group;" ::: "memory")
#define CP_WAIT(N)   asm volatile("cp.async.wait_group %0;" :: "n"(N) : "memory")

// Vertical 11-tap conv over 18 ring slots -> 8 output rows + SSIM accumulate.
// BASE = starting ring slot (mod 48), compile-time.
template <int BASE>
__device__ __forceinline__ void vert8(const float4* __restrict__ ring, int vswz,
                                      const u64* __restrict__ wp, float& acc)
{
    u64 aSD[8], aSQ[8];
    #pragma unroll
    for (int o = 0; o < 8; o++) { aSD[o] = 0ull; aSQ[o] = 0ull; }
    #pragma unroll
    for (int r = 0; r < 18; r++) {
        const int slot = (BASE + r) % 48;            // compile-time
        ulonglong2 v = *reinterpret_cast<const ulonglong2*>(ring + slot * RW4 + vswz);
        #pragma unroll
        for (int o = 0; o < 8; o++) {
            const int t = r - o;
            if (t >= 0 && t <= 10) {
                const int m = (t < 6) ? t : 10 - t;
                aSD[o] = ffma2(v.x, wp[m], aSD[o]);
                aSQ[o] = ffma2(v.y, wp[m], aSQ[o]);
            }
        }
    }
    #pragma unroll
    for (int o = 0; o < 8; o++) {
        float mus_sq, mud_sq, es, ed;
        upk(mus_sq, mud_sq, fmul2(aSD[o], aSD[o]));
        upk(es, ed, aSQ[o]);
        const float mu12  = 0.25f * (mus_sq - mud_sq);   // mu1*mu2
        const float musum = 0.5f  * (mus_sq + mud_sq);   // mu1^2+mu2^2
        const float cross = 0.25f * (es - ed);           // conv(x*y)
        const float sqsum = 0.5f  * (es + ed);           // conv(x^2)+conv(y^2)
        const float sigma12 = cross - mu12;
        const float sigsum  = sqsum - musum;
        const float num = (2.f * mu12 + C1c) * (2.f * sigma12 + C2c);
        const float den = (musum + C1c) * (sigsum + C2c);
        acc += __fdividef(num, den);
    }
}

__global__ void __launch_bounds__(256, 3) ssim_main(const float* __restrict__ img1,
                                                    const float* __restrict__ img2,
                                                    float* __restrict__ out)
{
    __shared__ float Araw[2][CH][RAWW];
    __shared__ float Braw[2][CH][RAWW];
    __shared__ float4 Ring[48][RW4];
    __shared__ float wsum[8];

    const float Wf[6] = {0.00102838f, 0.00759877f, 0.03600077f,
                         0.10936070f, 0.21300552f, 0.26601174f};
    u64 wp[6];
    #pragma unroll
    for (int i = 0; i < 6; i++) wp[i] = pk(Wf[i], Wf[i]);

    const int tid   = threadIdx.x;
    const int x0    = blockIdx.x * SW;
    const int segY  = blockIdx.y * 64;
    const int plane = blockIdx.z;
    const float* p1 = img1 + (size_t)plane * (size_t)(WI * HI);
    const float* p2 = img2 + (size_t)plane * (size_t)(WI * HI);

    uint32_t uA, uB;
    { uint32_t t;
      asm("{ .reg .u64 x; cvta.to.shared.u64 x, %1; cvt.u32.u64 %0, x; }"
          : "=r"(t) : "l"(&Araw[0][0][0])); uA = t;
      asm("{ .reg .u64 x; cvta.to.shared.u64 x, %1; cvt.u32.u64 %0, x; }"
          : "=r"(t) : "l"(&Braw[0][0][0])); uB = t; }

    const int hrow = tid >> 4;           // 0..15
    const int hcg  = tid & 15;           // 0..15 (4 outputs each)
    const int vx   = tid & 63;
    const int vrg  = tid >> 6;           // 0..3
    const int vswz = SWZ4(vx);
    const float4* ringp = &Ring[0][0];

    // ---- hoisted per-thread cp.async geometry (chunk-invariant) ----
    // units u = tid, tid+256 (u < 640); u>=320 -> img2
    int   cRi[3], cGxi[3];
    bool  cValid[3], cColOK[3];
    const float* cBase[3];
    uint32_t cDst[3];
    #pragma unroll
    for (int i = 0; i < 3; i++) {
        int u = tid + i * 256;
        cValid[i] = (u < 640);
        int im = (u >= 320) ? 1 : 0;
        int v  = u - im * 320;
        int r  = v / 20;
        int c4 = v - r * 20;
        cRi[i]   = r;
        cGxi[i]  = x0 - 8 + c4 * 4;
        cColOK[i] = ((unsigned)cGxi[i] < (unsigned)WI);
        cBase[i] = im ? p2 : p1;
        cDst[i]  = (im ? uB : uA) + (uint32_t)((r * RAWW + c4 * 4) * 4);
    }

    float acc = 0.f;

    auto issueChunk = [&](int c) {
        const int bufOff = (c & 1) * (CH * RAWW * 4);
        const int yB = segY + c * CH - 5;
        #pragma unroll
        for (int i = 0; i < 3; i++) {
            if (cValid[i]) {
                int yy = yB + cRi[i];
                bool inb = cColOK[i] && ((unsigned)yy < (unsigned)HI);
                const float* src = cBase[i] +
                    (size_t)(inb ? yy : 0) * WI + (inb ? cGxi[i] : 0);
                cpasync16(cDst[i] + bufOff, src, inb ? 16 : 0);
            }
        }
        CP_COMMIT();
    };

    // horizontal conv of chunk c (compile-time): raw -> ring slots (16c mod 48)+hrow
    auto horiz = [&](int c) {
        const int buf  = c & 1;
        const int slot = (16 * c) % 48 + hrow;
        u64 aSD[4] = {0ull, 0ull, 0ull, 0ull};
        u64 aSQ[4] = {0ull, 0ull, 0ull, 0ull};
        #pragma unroll
        for (int b = 0; b < 5; b++) {
            float4 av = *reinterpret_cast<const float4*>(&Araw[buf][hrow][(hcg + b) * 4]);
            float4 bv = *reinterpret_cast<const float4*>(&Braw[buf][hrow][(hcg + b) * 4]);
            const float ae[4] = {av.x, av.y, av.z, av.w};
            const float be[4] = {bv.x, bv.y, bv.z, bv.w};
            #pragma unroll
            for (int e = 0; e < 4; e++) {
                const int q = 4 * b + e;
                if (q < 3 || q > 16) continue;
                const u64 sd = pk(ae[e] + be[e], ae[e] - be[e]);
                const u64 sq = fmul2(sd, sd);
                #pragma unroll
                for (int o = 0; o < 4; o++) {
                    const int t = q - 3 - o;
                    if (t >= 0 && t <= 10) {
                        const int m = (t < 6) ? t : 10 - t;
                        aSD[o] = ffma2(sd, wp[m], aSD[o]);
                        aSQ[o] = ffma2(sq, wp[m], aSQ[o]);
                    }
                }
            }
        }
        #pragma unroll
        for (int o = 0; o < 4; o++) {
            ulonglong2 st; st.x = aSD[o]; st.y = aSQ[o];
            *reinterpret_cast<ulonglong2*>(&Ring[slot][SWZ4(hcg * 4 + o)]) = st;
        }
    };

    // ---- pipeline ----
    issueChunk(0);
    issueChunk(1);
    CP_WAIT(1); __syncthreads();
    horiz(0);
    __syncthreads();                 // raw buf0 free
    issueChunk(2);
    CP_WAIT(1); __syncthreads();     // raw1 visible
    horiz(1);
    __syncthreads();                 // raw buf1 free
    issueChunk(3);
    CP_WAIT(1); __syncthreads();     // raw2 visible
    horiz(2);
    __syncthreads();                 // ring slots 0..47 complete; raw buf0 free
    issueChunk(4);

    // vertical pass 0: output rows segY+0..31 (overlaps chunk-4 copy)
    if      (vrg == 0) vert8<0 >(ringp, vswz, wp, acc);
    else if (vrg == 1) vert8<8 >(ringp, vswz, wp, acc);
    else if (vrg == 2) vert8<16>(ringp, vswz, wp, acc);
    else               vert8<24>(ringp, vswz, wp, acc);

    CP_WAIT(1); __syncthreads();     // vert0 reads done (WAR) + raw3 visible
    horiz(3);                        // writes slots 0..15
    CP_WAIT(0); __syncthreads();     // raw4 visible; horiz(3) writes ordered
    horiz(4);                        // writes slots 16..31
    __syncthreads();

    // vertical pass 1: output rows segY+32..63
    if      (vrg == 0) vert8<32>(ringp, vswz, wp, acc);
    else if (vrg == 1) vert8<40>(ringp, vswz, wp, acc);
    else if (vrg == 2) vert8<0 >(ringp, vswz, wp, acc);
    else               vert8<8 >(ringp, vswz, wp, acc);

    // ---- block reduction -> one double atomic per block ----
    #pragma unroll
    for (int off = 16; off > 0; off >>= 1)
        acc += __shfl_down_sync(0xffffffffu, acc, off);
    if ((tid & 31) == 0) wsum[tid >> 5] = acc;
    __syncthreads();
    if (tid == 0) {
        float s = 0.f;
        #pragma unroll
        for (int i = 0; i < 8; i++) s += wsum[i];
        atomicAdd(&g_accum, (double)s);
        __threadfence();
        unsigned t = atomicAdd(&g_done, 1u);
        if (t == NBLK - 1) {
            double tot = atomicAdd(&g_accum, 0.0);
            out[0] = (float)(1.0 - tot * (1.0 / NPIX));
            g_accum = 0.0;
            g_done  = 0u;
        }
    }
}

extern "C" void kernel_launch(void* const* d_in, const int* in_sizes, int n_in,
                              void* d_out, int out_size) {
    (void)in_sizes; (void)n_in; (void)out_size;
    const float* img1 = (const float*)d_in[0];
    const float* img2 = (const float*)d_in[1];
    ssim_main<<<dim3(WI / SW, HI / 64, 96), 256>>>(img1, img2, (float*)d_out);
}

// round 7
// speedup vs baseline: 1.1746x; 1.1746x over previous
#include <cuda_runtime.h>
#include <cstdint>

// SSIM loss, separable Gaussian 11x11 on fields {s,d,s^2,d^2}, s=x+y, d=x-y.
// R5 structure (4 CTAs/SM, 32-slot ring, vert 4 rows/thread, cp.async depth-2)
// + hoisted cp.async geometry + trimmed horizontal LDS (.64/.128 mix).

namespace {
constexpr int WI = 512, HI = 512;
constexpr int SW = 64;              // strip width
constexpr int CH = 16;              // rows per chunk
constexpr int NCH = 4;              // output chunks per block (64 rows)
constexpr int RAWW = 84;            // raw row stride in floats (80 used)
constexpr float C1c = 1e-4f;
constexpr float C2c = 9e-4f;
constexpr double NPIX = 25165824.0; // 32*3*512*512
constexpr unsigned NBLK = 8 * 8 * 96;
}

__device__ double g_accum;
__device__ unsigned g_done;

using u64 = unsigned long long;

__device__ __forceinline__ u64 pk(float a, float b) {
    u64 r; asm("mov.b64 %0, {%1, %2};" : "=l"(r) : "f"(a), "f"(b)); return r;
}
__device__ __forceinline__ void upk(float& a, float& b, u64 v) {
    asm("mov.b64 {%0, %1}, %2;" : "=f"(a), "=f"(b) : "l"(v));
}
__device__ __forceinline__ u64 ffma2(u64 a, u64 b, u64 c) {
    u64 d; asm("fma.rn.f32x2 %0, %1, %2, %3;" : "=l"(d) : "l"(a), "l"(b), "l"(c));
    return d;
}
__device__ __forceinline__ u64 fmul2(u64 a, u64 b) {
    u64 d; asm("mul.rn.f32x2 %0, %1, %2;" : "=l"(d) : "l"(a), "l"(b));
    return d;
}
__device__ __forceinline__ int SWZ4(int c) { return c ^ (((c) >> 3) & 7); }

__device__ __forceinline__ void cpasync16(uint32_t dst, const void* src, int srcsize) {
    asm volatile("cp.async.cg.shared.global [%0], [%1], 16, %2;"
                 :: "r"(dst), "l"(src), "r"(srcsize) : "memory");
}
#define CP_COMMIT()  asm volatile("cp.async.commit_group;" ::: "memory")
#define CP_WAIT(N)   asm volatile("cp.async.wait_group %0;" :: "n"(N) : "memory")

__global__ void __launch_bounds__(256, 4) ssim_main(const float* __restrict__ img1,
                                                    const float* __restrict__ img2,
                                                    float* __restrict__ out)
{
    __shared__ float Araw[2][CH][RAWW];   // raw img1 rows (double buffer)
    __shared__ float Braw[2][CH][RAWW];   // raw img2 rows
    __shared__ float4 Ring[32][64];       // {S,D,S2,D2} per px
    __shared__ float wsum[8];

    const float Wf[6] = {0.00102838f, 0.00759877f, 0.03600077f,
                         0.10936070f, 0.21300552f, 0.26601174f};
    u64 wp[6];
    #pragma unroll
    for (int i = 0; i < 6; i++) wp[i] = pk(Wf[i], Wf[i]);

    const int tid   = threadIdx.x;
    const int x0    = blockIdx.x * SW;
    const int segY  = blockIdx.y * (CH * NCH);
    const int plane = blockIdx.z;
    const float* p1 = img1 + (size_t)plane * (size_t)(WI * HI);
    const float* p2 = img2 + (size_t)plane * (size_t)(WI * HI);

    uint32_t uA, uB;
    { uint32_t t;
      asm("{ .reg .u64 x; cvta.to.shared.u64 x, %1; cvt.u32.u64 %0, x; }"
          : "=r"(t) : "l"(&Araw[0][0][0])); uA = t;
      asm("{ .reg .u64 x; cvta.to.shared.u64 x, %1; cvt.u32.u64 %0, x; }"
          : "=r"(t) : "l"(&Braw[0][0][0])); uB = t; }

    const int hrow = tid >> 4;           // 0..15
    const int hcg  = tid & 15;           // 0..15 (4 outputs each)
    const int vx   = tid & 63;
    const int vrg  = tid >> 6;           // 0..3
    const int vswz = SWZ4(vx);
    const int vb4  = vrg * 4;

    // ---- hoisted per-thread cp.async geometry (chunk-invariant) ----
    int   cRi[3], cGxi[3];
    bool  cValid[3], cColOK[3];
    const float* cBase[3];
    uint32_t cDst[3];
    #pragma unroll
    for (int i = 0; i < 3; i++) {
        int u = tid + i * 256;
        cValid[i] = (u < 640);
        int im = (u >= 320) ? 1 : 0;
        int v  = u - im * 320;
        int r  = v / 20;
        int c4 = v - r * 20;
        cRi[i]   = r;
        cGxi[i]  = x0 - 8 + c4 * 4;
        cColOK[i] = ((unsigned)cGxi[i] < (unsigned)WI);
        cBase[i] = im ? p2 : p1;
        cDst[i]  = (im ? uB : uA) + (uint32_t)((r * RAWW + c4 * 4) * 4);
    }

    float acc = 0.f;

    auto issueChunk = [&](int c) {
        const int bufOff = (c & 1) * (CH * RAWW * 4);
        const int yB = segY + c * CH - 5;
        #pragma unroll
        for (int i = 0; i < 3; i++) {
            if (cValid[i]) {
                int yy = yB + cRi[i];
                bool inb = cColOK[i] && ((unsigned)yy < (unsigned)HI);
                const float* src = cBase[i] +
                    (size_t)(inb ? yy : 0) * WI + (inb ? cGxi[i] : 0);
                cpasync16(cDst[i] + bufOff, src, inb ? 16 : 0);
            }
        }
        CP_COMMIT();
    };

    // horizontal conv of chunk p (compile-time): raw -> ring
    // Only staged px 3..16 carry taps: load .64(px2-3) + 3x.128(px4-15) + .64(px16-17).
    auto horiz = [&](int p) {
        const int buf  = p & 1;
        const int slot = (((p & 1) << 4) + 27 + hrow) & 31;   // (16p-5+hrow) mod 32
        const float* rA = &Araw[buf][hrow][hcg * 4];
        const float* rB = &Braw[buf][hrow][hcg * 4];

        u64 aSD[4] = {0ull, 0ull, 0ull, 0ull};
        u64 aSQ[4] = {0ull, 0ull, 0ull, 0ull};

        auto tap = [&](int q, float a, float b) {   // q = staged px index (3..16)
            const u64 sd = pk(a + b, a - b);
            const u64 sq = fmul2(sd, sd);
            #pragma unroll
            for (int o = 0; o < 4; o++) {
                const int t = q - 3 - o;
                if (t >= 0 && t <= 10) {
                    const int m = (t < 6) ? t : 10 - t;
                    aSD[o] = ffma2(sd, wp[m], aSD[o]);
                    aSQ[o] = ffma2(sq, wp[m], aSQ[o]);
                }
            }
        };

        {   // px 3 (y-half of float2 at px2)
            float2 a = *reinterpret_cast<const float2*>(rA + 2);
            float2 b = *reinterpret_cast<const float2*>(rB + 2);
            tap(3, a.y, b.y);
        }
        #pragma unroll
        for (int g = 0; g < 3; g++) {   // px 4..15
            float4 a = *reinterpret_cast<const float4*>(rA + 4 + g * 4);
            float4 b = *reinterpret_cast<const float4*>(rB + 4 + g * 4);
            tap(4 + g * 4 + 0, a.x, b.x);
            tap(4 + g * 4 + 1, a.y, b.y);
            tap(4 + g * 4 + 2, a.z, b.z);
            tap(4 + g * 4 + 3, a.w, b.w);
        }
        {   // px 16 (x-half of float2 at px16)
            float2 a = *reinterpret_cast<const float2*>(rA + 16);
            float2 b = *reinterpret_cast<const float2*>(rB + 16);
            tap(16, a.x, b.x);
        }

        #pragma unroll
        for (int o = 0; o < 4; o++) {
            ulonglong2 st; st.x = aSD[o]; st.y = aSQ[o];
            *reinterpret_cast<ulonglong2*>(&Ring[slot][SWZ4(hcg * 4 + o)]) = st;
        }
    };

    // vertical conv + SSIM for chunk k (compile-time), 4 rows/thread
    auto vert = [&](int k) {
        u64 aSD[4] = {0ull, 0ull, 0ull, 0ull};
        u64 aSQ[4] = {0ull, 0ull, 0ull, 0ull};
        #pragma unroll
        for (int r = 0; r < 14; r++) {
            const int slot = (k * CH - 5 + r + vb4 + 32) & 31;
            ulonglong2 v = *reinterpret_cast<const ulonglong2*>(&Ring[slot][vswz]);
            #pragma unroll
            for (int o = 0; o < 4; o++) {
                const int t = r - o;
                if (t >= 0 && t <= 10) {
                    const int m = (t < 6) ? t : 10 - t;
                    aSD[o] = ffma2(v.x, wp[m], aSD[o]);
                    aSQ[o] = ffma2(v.y, wp[m], aSQ[o]);
                }
            }
        }
        #pragma unroll
        for (int o = 0; o < 4; o++) {
            float mus_sq, mud_sq, es, ed;
            upk(mus_sq, mud_sq, fmul2(aSD[o], aSD[o]));
            upk(es, ed, aSQ[o]);
            const float mu12  = 0.25f * (mus_sq - mud_sq);
            const float musum = 0.5f  * (mus_sq + mud_sq);
            const float cross = 0.25f * (es - ed);
            const float sqsum = 0.5f  * (es + ed);
            const float sigma12 = cross - mu12;
            const float sigsum  = sqsum - musum;
            const float num = (2.f * mu12 + C1c) * (2.f * sigma12 + C2c);
            const float den = (musum + C1c) * (sigsum + C2c);
            acc += __fdividef(num, den);
        }
    };

    // ---- prologue ----
    issueChunk(0);
    issueChunk(1);
    CP_WAIT(1);
    __syncthreads();
    horiz(0);
    __syncthreads();
    issueChunk(2);

    // ---- pipelined main loop (fully unrolled) ----
    #pragma unroll
    for (int k = 0; k < NCH; k++) {
        if (k < 3) { CP_WAIT(1); } else { CP_WAIT(0); }   // g_{k+1} done
        __syncthreads();                                   // raw visible; ring reads done
        horiz(k + 1);
        __syncthreads();
        if (k == 0) issueChunk(3);
        if (k == 1) issueChunk(4);
        vert(k);                                           // overlaps in-flight copies
    }

    // ---- block reduction -> one double atomic per block ----
    #pragma unroll
    for (int off = 16; off > 0; off >>= 1)
        acc += __shfl_down_sync(0xffffffffu, acc, off);
    if ((tid & 31) == 0) wsum[tid >> 5] = acc;
    __syncthreads();
    if (tid == 0) {
        float s = 0.f;
        #pragma unroll
        for (int i = 0; i < 8; i++) s += wsum[i];
        atomicAdd(&g_accum, (double)s);
        __threadfence();
        unsigned t = atomicAdd(&g_done, 1u);
        if (t == NBLK - 1) {
            double tot = atomicAdd(&g_accum, 0.0);
            out[0] = (float)(1.0 - tot * (1.0 / NPIX));
            g_accum = 0.0;
            g_done  = 0u;
        }
    }
}

extern "C" void kernel_launch(void* const* d_in, const int* in_sizes, int n_in,
                              void* d_out, int out_size) {
    (void)in_sizes; (void)n_in; (void)out_size;
    const float* img1 = (const float*)d_in[0];
    const float* img2 = (const float*)d_in[1];
    ssim_main<<<dim3(WI / SW, HI / (CH * NCH), 96), 256>>>(img1, img2, (float*)d_out);
}